// round 1
// baseline (speedup 1.0000x reference)
#include <cuda_runtime.h>

// Problem constants (fixed by the reference):
// N=2, C=2, H=W=D=64, R=3, WEIGHT=1, SIGMA_XY=6, SIGMA_IMG=0.1
static constexpr int H = 64, W = 64, D = 64, NN = 2;
static constexpr int NBLK = 2 * 64 * 4;   // n * i * jc  = 512 blocks

__device__ float g_partials[NBLK];

__device__ __forceinline__ float ex2f(float x) {
    float y;
    asm("ex2.approx.ftz.f32 %0, %1;" : "=f"(y) : "f"(x));
    return y;
}

// KS = sqrt(50 * log2(e));  KS^2 * ds^2 = 50*log2e*ds^2
#define KS 8.4932180864f
#define HALFL2E 0.0200373478f  /* 0.5/36 * log2(e) */

__global__ __launch_bounds__(256) void crf_main(
    const float* __restrict__ yg, const float* __restrict__ sg)
{
    const int d4 = threadIdx.x;          // 0..15  (4 d-values each)
    const int ty = threadIdx.y;          // 0..15
    const int b  = blockIdx.x;
    const int jc = b & 3;
    const int i  = (b >> 2) & 63;
    const int n  = b >> 8;
    const int j  = jc * 16 + ty;

    const float4* __restrict__ s4 = (const float4*)sg;
    const float4* __restrict__ y4 = (const float4*)yg;

    // sample layout: ((n*H + i)*W + j)*D + d   -> float4 idx
    const int bs = (n * H + i) * (W * 16) + j * 16 + d4;
    // y channel 0: (((n*2 + 0)*H + i)*W + j)*D + d
    const int by = (n * 2 * H + i) * (W * 16) + j * 16 + d4;

    const float4 sc = s4[bs];
    const float4 yc = y4[by];

    // negated scaled sample values: na = -KS * s_center
    const float na0 = -KS * sc.x, na1 = -KS * sc.y;
    const float na2 = -KS * sc.z, na3 = -KS * sc.w;
    const float yp0 = yc.x, yp1 = yc.y, yp2 = yc.z, yp3 = yc.w;
    const float m0 = -2.0f * yp0, m1 = -2.0f * yp1;
    const float m2 = -2.0f * yp2, m3 = -2.0f * yp3;

    float acc = 0.0f;

    // Unordered in-bounds pairs: positive offsets only, doubled at the end.
    #pragma unroll
    for (int di = 0; di <= 3; ++di) {
        #pragma unroll
        for (int dj = -3; dj <= 3; ++dj) {
            if (di == 0 && dj <= 0) continue;   // only (0,1..3) and (1..3, -3..3)
            const float lw = -(float)(di * di + dj * dj) * HALFL2E;
            const int i2 = i + di;
            const int j2 = j + dj;
            if (i2 < H && (unsigned)j2 < (unsigned)W) {
                const int off = (di * W + dj) * 16;
                const float4 sq = s4[bs + off];
                const float4 yq = y4[by + off];

                {   float t = fmaf(KS, sq.x, na0);
                    float k = ex2f(fmaf(t, -t, lw));
                    float u = fmaf(m0, yq.x, yp0 + yq.x);
                    acc = fmaf(k, u, acc); }
                {   float t = fmaf(KS, sq.y, na1);
                    float k = ex2f(fmaf(t, -t, lw));
                    float u = fmaf(m1, yq.y, yp1 + yq.y);
                    acc = fmaf(k, u, acc); }
                {   float t = fmaf(KS, sq.z, na2);
                    float k = ex2f(fmaf(t, -t, lw));
                    float u = fmaf(m2, yq.z, yp2 + yq.z);
                    acc = fmaf(k, u, acc); }
                {   float t = fmaf(KS, sq.w, na3);
                    float k = ex2f(fmaf(t, -t, lw));
                    float u = fmaf(m3, yq.w, yp3 + yq.w);
                    acc = fmaf(k, u, acc); }
            }
        }
    }
    acc *= 2.0f;   // unordered -> directed

    // Out-of-bounds slots: neighbor features are zero-padded, so
    // k_oob = exp(-0.5*(fr^2+fc^2+fs^2)), identical for every OOB slot of a pixel.
    {
        const int ir = min(i + 3, H - 1) - max(i - 3, 0) + 1;
        const int ic = min(j + 3, W - 1) - max(j - 3, 0) + 1;
        const float cnt = (float)(49 - ir * ic);
        if (cnt > 0.0f) {
            const float cij = -(float)(i * i + j * j) * HALFL2E;
            float e = ex2f(fmaf(na0, -na0, cij))
                    + ex2f(fmaf(na1, -na1, cij))
                    + ex2f(fmaf(na2, -na2, cij))
                    + ex2f(fmaf(na3, -na3, cij));
            acc = fmaf(cnt, e, acc);
        }
    }

    // Deterministic block tree reduction
    __shared__ float red[256];
    const int tid = ty * 16 + d4;
    red[tid] = acc;
    __syncthreads();
    #pragma unroll
    for (int offr = 128; offr > 0; offr >>= 1) {
        if (tid < offr) red[tid] += red[tid + offr];
        __syncthreads();
    }
    if (tid == 0) g_partials[b] = red[0];
}

__global__ __launch_bounds__(NBLK) void crf_reduce(float* __restrict__ out)
{
    __shared__ double red[NBLK];
    const int tid = threadIdx.x;
    red[tid] = (double)g_partials[tid];
    __syncthreads();
    #pragma unroll
    for (int offr = NBLK / 2; offr > 0; offr >>= 1) {
        if (tid < offr) red[tid] += red[tid + offr];
        __syncthreads();
    }
    if (tid == 0)
        out[0] = (float)(red[0] / (double)(NN * D * H * W));
}

extern "C" void kernel_launch(void* const* d_in, const int* in_sizes, int n_in,
                              void* d_out, int out_size)
{
    const float* y = (const float*)d_in[0];   // (2,2,64,64,64) softmax
    const float* s = (const float*)d_in[1];   // (2,1,64,64,64) sample
    // Defensive: identify by element count (y has 2 channels -> 2097152 elems)
    if (n_in >= 2 && in_sizes[0] == 2 * 1 * H * W * D) {
        const float* tmp = y; y = s; s = tmp;
    }

    dim3 blk(16, 16);
    crf_main<<<NBLK, blk>>>(y, s);
    crf_reduce<<<1, NBLK>>>((float*)d_out);
}